// round 16
// baseline (speedup 1.0000x reference)
#include <cuda_runtime.h>

#define BN    32768      // B*N
#define NPTS  8192
#define KNN   16
#define BINS  4096
#define XLO   (-6.0f)
#define BSCALE (BINS / 12.0f)
#define DELTA  (12.0f / BINS)
#define WPAIRS 1536      // window pairs (3072 candidates)
#define QTR    384       // pairs per quarter (3 tiles of 128)
#define CAP    24        // per-lane survivor stack capacity

typedef unsigned long long ull;

__device__ float4 g_pts[BN];
__device__ int    g_hist[4 * BINS];
__device__ int    g_off [4 * BINS];
__device__ float4 g_sx  [BN];
__device__ int    g_sidx[BN];
__device__ ulonglong2 g_ta[BN / 2];
__device__ ulonglong2 g_tb[BN / 2];
__device__ float  g_T  [BN];                    // warm threshold, >= true d16
__device__ ull    g_pk[(size_t)BN * 4 * KNN];   // per-quarter sorted key lists
__device__ float  g_thr[BN];                    // window d16 (fallback threshold)
__device__ int    g_flag[BN];
__device__ int    g_idx[BN * KNN];
__device__ float  g_lt[(size_t)BN * 192];

#define DINF 3.4e38f

// ---- packed f32x2 helpers (each lane independent exact fp32) --------------
__device__ __forceinline__ ull pk(float a, float b) {
    ull r; asm("mov.b64 %0, {%1,%2};" : "=l"(r) : "f"(a), "f"(b)); return r;
}
__device__ __forceinline__ void upk(ull v, float& a, float& b) {
    asm("mov.b64 {%0,%1}, %2;" : "=f"(a), "=f"(b) : "l"(v));
}
__device__ __forceinline__ ull fma2(ull a, ull b, ull c) {
    ull r; asm("fma.rn.f32x2 %0, %1, %2, %3;" : "=l"(r) : "l"(a), "l"(b), "l"(c)); return r;
}
__device__ __forceinline__ ull mul2(ull a, ull b) {
    ull r; asm("mul.rn.f32x2 %0, %1, %2;" : "=l"(r) : "l"(a), "l"(b)); return r;
}
__device__ __forceinline__ ull add2(ull a, ull b) {
    ull r; asm("add.rn.f32x2 %0, %1, %2;" : "=l"(r) : "l"(a), "l"(b)); return r;
}

// monotone order-preserving float -> u32 (+0.0f normalizes -0)
__device__ __forceinline__ unsigned fmap(float f) {
    unsigned b = __float_as_uint(f + 0.0f);
    return b ^ ((unsigned)((int)b >> 31) | 0x80000000u);
}
__device__ __forceinline__ float finv(unsigned u) {
    unsigned b = (u & 0x80000000u) ? (u ^ 0x80000000u) : ~u;
    return __uint_as_float(b);
}
__device__ __forceinline__ ull mkkey(float d, unsigned idx) {
    return (((ull)fmap(d)) << 32) | idx;
}

__device__ __forceinline__ int binof(float x) {
    int b = (int)((x - XLO) * BSCALE);
    return min(BINS - 1, max(0, b));
}

// sorted insert of u64 key into ascending 16-list (shift chain)
__device__ __forceinline__ void kins16(ull k, ull* B) {
    if (k >= B[15]) return;
    bool cs = true;
#pragma unroll
    for (int s = 15; s > 0; --s) {
        bool cp = k < B[s - 1];
        ull nb = cp ? B[s - 1] : (cs ? k : B[s]);
        B[s] = nb;
        cs = cp;
    }
    if (cs) B[0] = k;
}

// drain per-lane smem stack into register list; returns new float threshold
__device__ __forceinline__ float drainK(int& cnt, ull* stk, int tid, ull* B) {
    for (int i = 0;; i++) {
        if (!__ballot_sync(0xffffffffu, i < cnt)) break;
        if (i < cnt) {
            ull e = stk[i * 128 + tid];
            if (e < B[15]) kins16(e, B);
        }
    }
    cnt = 0;
    unsigned fk = (unsigned)(B[15] >> 32);
    return (fk == 0xFFFFFFFFu) ? DINF : finv(fk);
}

// ---------------------------------------------------------------------------
// 0. zero histogram
// ---------------------------------------------------------------------------
__global__ void zero_kernel() {
    int i = blockIdx.x * 256 + threadIdx.x;
    g_hist[i] = 0;
}

// ---------------------------------------------------------------------------
// 1. pack (x,y,z, sq) + histogram; sq = ((x*x)+(y*y))+(z*z) separately rounded
//    (exact XLA replication -- LOAD-BEARING)
// ---------------------------------------------------------------------------
__global__ void pack_kernel(const float* __restrict__ xytp) {
    int i = blockIdx.x * blockDim.x + threadIdx.x;
    float4 p = ((const float4*)xytp)[i];
    float xx = __fmul_rn(p.x, p.x);
    float yy = __fmul_rn(p.y, p.y);
    float zz = __fmul_rn(p.z, p.z);
    p.w = __fadd_rn(__fadd_rn(xx, yy), zz);
    g_pts[i] = p;
    atomicAdd(&g_hist[(i >> 13) * BINS + binof(p.x)], 1);
}

// ---------------------------------------------------------------------------
// 2. exclusive scan of per-batch histogram
// ---------------------------------------------------------------------------
__global__ void __launch_bounds__(1024) scan_kernel() {
    __shared__ int sv[1024];
    int b = blockIdx.x, t = threadIdx.x;
    int base = b * BINS + t * 4;
    int a0 = g_hist[base], a1 = g_hist[base + 1], a2 = g_hist[base + 2], a3 = g_hist[base + 3];
    int s = a0 + a1 + a2 + a3;
    sv[t] = s;
    __syncthreads();
    for (int off = 1; off < 1024; off <<= 1) {
        int v = (t >= off) ? sv[t - off] : 0;
        __syncthreads();
        sv[t] += v;
        __syncthreads();
    }
    int excl = sv[t] - s;
    g_off[base]     = excl;
    g_off[base + 1] = excl + a0;
    g_off[base + 2] = excl + a0 + a1;
    g_off[base + 3] = excl + a0 + a1 + a2;
}

// ---------------------------------------------------------------------------
// 3. scatter into x-bin order
// ---------------------------------------------------------------------------
__global__ void scatter_kernel() {
    int i = blockIdx.x * blockDim.x + threadIdx.x;
    int b = i >> 13;
    float4 p = g_pts[i];
    int pos = atomicAdd(&g_off[b * BINS + binof(p.x)], 1);
    g_sx  [b * NPTS + pos] = p;
    g_sidx[b * NPTS + pos] = i & (NPTS - 1);
}

// ---------------------------------------------------------------------------
// 4. pair-pack scattered points
// ---------------------------------------------------------------------------
__global__ void repack_kernel() {
    int j = blockIdx.x * blockDim.x + threadIdx.x;
    float4 p0 = g_sx[2 * j];
    float4 p1 = g_sx[2 * j + 1];
    ulonglong2 va, vb;
    va.x = pk(p0.x, p1.x);  va.y = pk(p0.y, p1.y);
    vb.x = pk(p0.z, p1.z);  vb.y = pk(p0.w, p1.w);
    g_ta[j] = va;  g_tb[j] = vb;
}

// ---------------------------------------------------------------------------
// 5. seed: WARP per query. 512-candidate x-window, exact distances, binary
//    search on fmap bits for T with count(d<=T) >= 16 in-window => T >= d16.
// ---------------------------------------------------------------------------
__global__ void __launch_bounds__(128) seed_kernel() {
    int b    = blockIdx.y;
    int wid  = threadIdx.x >> 5, lane = threadIdx.x & 31;
    int p    = blockIdx.x * 4 + wid;
    const ulonglong2* TA = g_ta + b * (NPTS / 2);
    const ulonglong2* TB = g_tb + b * (NPTS / 2);
    float4 me = g_sx[b * NPTS + p];
    ull m2x = pk(-2.0f * me.x, -2.0f * me.x);   // exact power-of-2 scale
    ull m2y = pk(-2.0f * me.y, -2.0f * me.y);
    ull m2z = pk(-2.0f * me.z, -2.0f * me.z);
    ull mw  = pk(me.w, me.w);

    int plo = min(max((p >> 1) - 128, 0), NPTS / 2 - 256);

    unsigned fm[16];
#pragma unroll
    for (int u = 0; u < 8; u++) {
        int j = plo + lane + 32 * u;            // coalesced across warp
        ulonglong2 A = TA[j], Z = TB[j];
        // exact reference arithmetic (validated bitwise):
        ull dn = fma2(m2z, Z.x, fma2(m2y, A.y, mul2(m2x, A.x)));
        ull dd = add2(add2(mw, Z.y), dn);
        float d0, d1; upk(dd, d0, d1);
        fm[2 * u]     = fmap(d0);
        fm[2 * u + 1] = fmap(d1);
    }

    unsigned lo = 0u, hi = 0xFFFFFFFFu;         // count(hi) = 512 >= 16
#pragma unroll
    for (int it = 0; it < 16; it++) {
        unsigned mid = lo + ((hi - lo) >> 1);
        int c = 0;
#pragma unroll
        for (int u = 0; u < 16; u++) c += (fm[u] <= mid);
        int tot = __reduce_add_sync(0xffffffffu, c);
        if (tot >= 16) hi = mid; else lo = mid + 1;
    }
    if (lane == 0) g_T[b * NPTS + p] = finv(hi);
}

// ---------------------------------------------------------------------------
// 6. windowed kNN, warm threshold + THRESHOLD-DRIVEN TILE SKIPPING.
//    Per 128-pair tile: all members lie in bins [bin(x_first), bin(x_last)]
//    (array is bin-ascending). If the x-gap from the query to that bin range
//    gives gap^2 > T + 1e-3, no member can beat T >= true d16 -> skip.
//    Block-uniform skip avoids staging; warp-uniform skip avoids compute.
// ---------------------------------------------------------------------------
__global__ void __launch_bounds__(128) knn_win_kernel() {
    __shared__ ulonglong2 ta[128], tb[128];
    __shared__ int2       si2[128];
    __shared__ ull        stk[CAP * 128];

    int tid = threadIdx.x;
    int b   = blockIdx.z;
    int qtr = blockIdx.y;
    int qb  = blockIdx.x * 128;
    int q   = qb + tid;

    const float4*     SX  = g_sx + b * NPTS;
    const ulonglong2* TA  = g_ta + b * (NPTS / 2);
    const ulonglong2* TB  = g_tb + b * (NPTS / 2);
    const int2*       SI2 = (const int2*)(g_sidx + b * NPTS);

    float4 me = SX[q];
    float  T  = g_T [b * NPTS + q];
    ull m2x = pk(-2.0f * me.x, -2.0f * me.x);   // exact power-of-2 scale
    ull m2y = pk(-2.0f * me.y, -2.0f * me.y);
    ull m2z = pk(-2.0f * me.z, -2.0f * me.z);
    ull mw  = pk(me.w, me.w);

    int W = min(max(qb / 2 + 32 - WPAIRS / 2, 0), NPTS / 2 - WPAIRS);
    int pbase = W + qtr * QTR;

    ull B[KNN];
#pragma unroll
    for (int s = 0; s < KNN; s++) B[s] = ~0ULL;
    float b15f = T;      // warm threshold
    int cnt = 0;

    for (int t0 = 0; t0 < QTR; t0 += 128) {
        int pj0 = pbase + t0;
        // tile bin range from boundary candidates (broadcast loads)
        float xf = SX[2 * pj0].x;
        float xl = SX[2 * pj0 + 255].x;
        int blo = binof(xf), bhi = binof(xl);
        float gapR = (XLO + blo * DELTA) - me.x;          // tile right of query
        float gapL = me.x - (XLO + (bhi + 1) * DELTA);    // tile left of query
        bool skip = ((blo >= 1        && gapR > 0.0f && gapR * gapR > T + 1e-3f) ||
                     (bhi <= BINS - 2 && gapL > 0.0f && gapL * gapL > T + 1e-3f));
        if (__syncthreads_and(skip)) continue;   // barrier + block-wide skip

        ta[tid]  = TA[pj0 + tid];
        tb[tid]  = TB[pj0 + tid];
        si2[tid] = SI2[pj0 + tid];
        __syncthreads();
        if (__all_sync(0xffffffffu, skip)) continue;   // warp-wide skip

#pragma unroll 4
        for (int j = 0; j < 128; j += 2) {
            ulonglong2 A0 = ta[j],     Z0 = tb[j];
            ulonglong2 A1 = ta[j + 1], Z1 = tb[j + 1];
            // exact reference arithmetic (validated bitwise):
            ull dn0 = fma2(m2z, Z0.x, fma2(m2y, A0.y, mul2(m2x, A0.x)));
            ull dn1 = fma2(m2z, Z1.x, fma2(m2y, A1.y, mul2(m2x, A1.x)));
            ull dd0 = add2(add2(mw, Z0.y), dn0);
            ull dd1 = add2(add2(mw, Z1.y), dn1);
            float d0, d1, d2, d3;
            upk(dd0, d0, d1);
            upk(dd1, d2, d3);
            int2 i0 = si2[j], i1 = si2[j + 1];
            if (d0 <= b15f) { stk[cnt * 128 + tid] = mkkey(d0, (unsigned)i0.x); cnt++; }
            if (d1 <= b15f) { stk[cnt * 128 + tid] = mkkey(d1, (unsigned)i0.y); cnt++; }
            if (d2 <= b15f) { stk[cnt * 128 + tid] = mkkey(d2, (unsigned)i1.x); cnt++; }
            if (d3 <= b15f) { stk[cnt * 128 + tid] = mkkey(d3, (unsigned)i1.y); cnt++; }
            if (__ballot_sync(0xffffffffu, cnt >= CAP - 4))
                b15f = fminf(T, drainK(cnt, stk, tid, B));
        }
        b15f = fminf(T, drainK(cnt, stk, tid, B));
    }

    size_t ob = ((size_t)(b * NPTS + q) * 4 + qtr) * KNN;
#pragma unroll
    for (int s = 0; s < KNN; s++) g_pk[ob + s] = B[s];
}

// ---------------------------------------------------------------------------
// 7. merge 4 quarter-lists -> top-16; exact window-sufficiency bound check.
// ---------------------------------------------------------------------------
__global__ void __launch_bounds__(128) merge_kernel() {
    int b = blockIdx.y;
    int qb = blockIdx.x * 128;
    int q  = qb + threadIdx.x;
    const ull* pk4 = g_pk + ((size_t)(b * NPTS + q) * 4) * KNN;

    ull B[KNN];
#pragma unroll
    for (int s = 0; s < KNN; s++) B[s] = ~0ULL;
#pragma unroll
    for (int c = 0; c < 4; c++) {
        for (int s = 0; s < KNN; s++) {
            ull k = pk4[c * KNN + s];
            if (k >= B[15]) break;           // lists sorted ascending
            kins16(k, B);
        }
    }

    float mex = g_sx[b * NPTS + q].x;
    int W = min(max(qb / 2 + 32 - WPAIRS / 2, 0), NPTS / 2 - WPAIRS);
    float d16 = finv((unsigned)(B[15] >> 32));

    bool safe_l = (W == 0);
    if (!safe_l) {
        int bl = binof(g_sx[b * NPTS + 2 * W].x);
        float gap = mex - (XLO + (bl + 1) * DELTA);
        safe_l = (bl < BINS - 1) && (gap > 0.0f) && (gap * gap > d16 + 1e-3f);
    }
    bool safe_r = (W + WPAIRS == NPTS / 2);
    if (!safe_r) {
        int br = binof(g_sx[b * NPTS + 2 * (W + WPAIRS) - 1].x);
        float gap = (XLO + br * DELTA) - mex;
        safe_r = (br > 0) && (gap > 0.0f) && (gap * gap > d16 + 1e-3f);
    }

    int orig = g_sidx[b * NPTS + q];
    int ob = (b * NPTS + orig) * KNN;
#pragma unroll
    for (int s = 0; s < KNN; s++)
        g_idx[ob + s] = (int)(unsigned)(B[s] & 0xffffffffu);
    g_flag[b * NPTS + q] = (safe_l && safe_r) ? 0 : 1;
    g_thr [b * NPTS + q] = d16;              // valid upper bound on true d16
}

// ---------------------------------------------------------------------------
// 8. fallback: warp-cooperative exact rescan for flagged queries.
// ---------------------------------------------------------------------------
__global__ void __launch_bounds__(128) fb_kernel() {
    __shared__ ull ssv[4][96];
    __shared__ int scnt[4];
    int tid = threadIdx.x, w = tid >> 5, lane = tid & 31;
    int b = blockIdx.y;
    int qbase = blockIdx.x * 128 + w * 32;
    int fl = g_flag[b * NPTS + qbase + lane];
    unsigned mask = __ballot_sync(0xffffffffu, fl != 0);
    if (!mask) return;

    const ulonglong2* TA  = g_ta + b * (NPTS / 2);
    const ulonglong2* TB  = g_tb + b * (NPTS / 2);
    const int2*       SI2 = (const int2*)(g_sidx + b * NPTS);

    while (mask) {
        int li = __ffs(mask) - 1; mask &= mask - 1;
        int fq = qbase + li;
        float4 me = g_sx[b * NPTS + fq];
        float  T  = g_thr[b * NPTS + fq];
        ull m2x = pk(-2.0f * me.x, -2.0f * me.x);
        ull m2y = pk(-2.0f * me.y, -2.0f * me.y);
        ull m2z = pk(-2.0f * me.z, -2.0f * me.z);
        ull mw  = pk(me.w, me.w);
        if (lane == 0) scnt[w] = 0;
        __syncwarp();
        for (int pj = lane; pj < NPTS / 2; pj += 32) {
            ulonglong2 A = TA[pj], Z = TB[pj];
            ull dn = fma2(m2z, Z.x, fma2(m2y, A.y, mul2(m2x, A.x)));
            ull dd = add2(add2(mw, Z.y), dn);
            float d0, d1; upk(dd, d0, d1);
            int2 ii = SI2[pj];
            if (d0 <= T) { int p = atomicAdd(&scnt[w], 1); if (p < 96) ssv[w][p] = mkkey(d0, (unsigned)ii.x); }
            if (d1 <= T) { int p = atomicAdd(&scnt[w], 1); if (p < 96) ssv[w][p] = mkkey(d1, (unsigned)ii.y); }
        }
        __syncwarp();
        if (lane == 0) {
            ull B[KNN];
#pragma unroll
            for (int s = 0; s < KNN; s++) B[s] = ~0ULL;
            int n = scnt[w];
            if (n <= 96) {
                for (int i = 0; i < n; i++) kins16(ssv[w][i], B);
            } else {                         // vanishing-probability overflow
                for (int pj = 0; pj < NPTS / 2; pj++) {
                    ulonglong2 A = TA[pj], Z = TB[pj];
                    ull dn = fma2(m2z, Z.x, fma2(m2y, A.y, mul2(m2x, A.x)));
                    ull dd = add2(add2(mw, Z.y), dn);
                    float d0, d1; upk(dd, d0, d1);
                    int2 ii = SI2[pj];
                    ull k0 = mkkey(d0, (unsigned)ii.x);
                    ull k1 = mkkey(d1, (unsigned)ii.y);
                    if (k0 < B[15]) kins16(k0, B);
                    if (k1 < B[15]) kins16(k1, B);
                }
            }
            int orig = g_sidx[b * NPTS + fq];
            int ob = (b * NPTS + orig) * KNN;
            for (int s = 0; s < KNN; s++)
                g_idx[ob + s] = (int)(unsigned)(B[s] & 0xffffffffu);
        }
        __syncwarp();
    }
}

// ---------------------------------------------------------------------------
// 9. lt = features @ lt_w + lt_b, f32x2, 4 independent partial accumulators
// ---------------------------------------------------------------------------
__global__ void __launch_bounds__(256) lt_kernel(const float* __restrict__ feat,
                                                 const float* __restrict__ w,
                                                 const float* __restrict__ bias) {
    __shared__ __align__(16) float fs[32][64];
    int row0 = blockIdx.x * 32;
    for (int i = threadIdx.x; i < 32 * 64; i += 256)
        fs[i >> 6][i & 63] = feat[row0 * 64 + i];
    __syncthreads();

    int c = threadIdx.x;
    if (c < 192) {
        ull w2[32];
#pragma unroll
        for (int k = 0; k < 32; k++)
            w2[k] = pk(w[(2 * k) * 192 + c], w[(2 * k + 1) * 192 + c]);
        float bc = bias[c];
        for (int r = 0; r < 32; r++) {
            ull a0 = pk(bc, 0.0f), a1 = pk(0.f, 0.f), a2 = a1, a3 = a1;
            const ull* fr = (const ull*)&fs[r][0];
#pragma unroll
            for (int k = 0; k < 32; k += 4) {
                a0 = fma2(fr[k],     w2[k],     a0);
                a1 = fma2(fr[k + 1], w2[k + 1], a1);
                a2 = fma2(fr[k + 2], w2[k + 2], a2);
                a3 = fma2(fr[k + 3], w2[k + 3], a3);
            }
            ull acc = add2(add2(a0, a1), add2(a2, a3));
            float ax, ay; upk(acc, ax, ay);
            g_lt[(size_t)(row0 + r) * 192 + c] = ax + ay;
        }
    }
}

// ---------------------------------------------------------------------------
// 10. fused: gather -> delta MLP -> LN -> softmax(k) -> output
// ---------------------------------------------------------------------------
__global__ void __launch_bounds__(128) fused_kernel(
    const float* __restrict__ xytp,
    const float* __restrict__ pe_w1, const float* __restrict__ pe_b1,
    const float* __restrict__ pe_w2, const float* __restrict__ pe_b2,
    const float* __restrict__ ln_g,  const float* __restrict__ ln_b,
    float* __restrict__ out)
{
    __shared__ float  W2s[64 * 64];
    __shared__ float4 rels[4][16];
    __shared__ __align__(16) float HS[4][64][20];

    int tid = threadIdx.x, w = tid >> 5, lane = tid & 31;
    for (int i = tid; i < 4096; i += 128) W2s[i] = pe_w2[i];

    int pt = blockIdx.x * 4 + w;
    int b  = pt >> 13;
    int c0 = lane, c1 = lane + 32;

    float w1a[4], w1b[4];
#pragma unroll
    for (int d = 0; d < 4; d++) { w1a[d] = pe_w1[d * 64 + c0]; w1b[d] = pe_w1[d * 64 + c1]; }
    float b10 = pe_b1[c0], b11 = pe_b1[c1];
    float b20 = pe_b2[c0], b21 = pe_b2[c1];
    float g0  = ln_g[c0],  g1  = ln_g[c1];
    float q0  = ln_b[c0],  q1  = ln_b[c1];

    const int* idxp = g_idx + pt * KNN;
    float4 ctr = ((const float4*)xytp)[pt];
    if (lane < 16) {
        int nb = idxp[lane];
        float4 p = ((const float4*)xytp)[b * NPTS + nb];
        rels[w][lane] = make_float4(ctr.x - p.x, ctr.y - p.y, ctr.z - p.z, ctr.w - p.w);
    }
    __syncthreads();

#pragma unroll
    for (int k = 0; k < KNN; k++) {
        float4 r = rels[w][k];
        float h0 = fmaf(r.w, w1a[3], fmaf(r.z, w1a[2], fmaf(r.y, w1a[1], fmaf(r.x, w1a[0], b10))));
        float h1 = fmaf(r.w, w1b[3], fmaf(r.z, w1b[2], fmaf(r.y, w1b[1], fmaf(r.x, w1b[0], b11))));
        HS[w][c0][k] = fmaxf(h0, 0.f);
        HS[w][c1][k] = fmaxf(h1, 0.f);
    }
    __syncwarp();

    ull d0p[8], d1p[8];
#pragma unroll
    for (int m = 0; m < 8; m++) { d0p[m] = pk(b20, b20); d1p[m] = pk(b21, b21); }
#pragma unroll 4
    for (int j = 0; j < 64; j++) {
        ull wv0 = pk(W2s[j * 64 + c0], W2s[j * 64 + c0]);
        ull wv1 = pk(W2s[j * 64 + c1], W2s[j * 64 + c1]);
        const ulonglong2* hr = (const ulonglong2*)&HS[w][j][0];
        ulonglong2 ha = hr[0], hb = hr[1];
        ull hp[4] = { ha.x, ha.y, hb.x, hb.y };
#pragma unroll
        for (int m = 0; m < 4; m++) {
            d0p[m] = fma2(hp[m], wv0, d0p[m]);
            d1p[m] = fma2(hp[m], wv1, d1p[m]);
        }
        ulonglong2 hc = hr[2], hd = hr[3];
        ull hq[4] = { hc.x, hc.y, hd.x, hd.y };
#pragma unroll
        for (int m = 0; m < 4; m++) {
            d0p[m + 4] = fma2(hq[m], wv0, d0p[m + 4]);
            d1p[m + 4] = fma2(hq[m], wv1, d1p[m + 4]);
        }
    }
    float d0[KNN], d1[KNN];
#pragma unroll
    for (int m = 0; m < 8; m++) {
        upk(d0p[m], d0[2 * m], d0[2 * m + 1]);
        upk(d1p[m], d1[2 * m], d1[2 * m + 1]);
    }

    const float* ltb = g_lt + (size_t)(b * NPTS) * 192;
    int n = pt & (NPTS - 1);
    float vp0 = ltb[(size_t)n * 192 + c0];
    float vp1 = ltb[(size_t)n * 192 + c1];

    float a0[KNN], a1[KNN], p0[KNN], p1[KNN];
#pragma unroll
    for (int k = 0; k < KNN; k++) {
        int nb = idxp[k];
        const float* lr = ltb + (size_t)nb * 192;
        float ps0 = lr[64 + c0],  ps1 = lr[64 + c1];
        float al0 = lr[128 + c0], al1 = lr[128 + c1];
        float pr0 = (vp0 - ps0) + d0[k];
        float pr1 = (vp1 - ps1) + d1[k];
        a0[k] = al0 + d0[k];
        a1[k] = al1 + d1[k];
        float sm = pr0 + pr1;
        float sq = fmaf(pr0, pr0, pr1 * pr1);
#pragma unroll
        for (int off = 16; off > 0; off >>= 1) {
            sm += __shfl_xor_sync(0xffffffffu, sm, off);
            sq += __shfl_xor_sync(0xffffffffu, sq, off);
        }
        float mu  = sm * (1.0f / 64.0f);
        float var = fmaf(-mu, mu, sq * (1.0f / 64.0f));
        float rs  = rsqrtf(var + 1e-5f);
        p0[k] = fmaf((pr0 - mu) * rs, g0, q0) * 0.125f;
        p1[k] = fmaf((pr1 - mu) * rs, g1, q1) * 0.125f;
    }

    float m0 = -3.4e38f, m1 = -3.4e38f;
#pragma unroll
    for (int k = 0; k < KNN; k++) { m0 = fmaxf(m0, p0[k]); m1 = fmaxf(m1, p1[k]); }
    float z0 = 0.f, z1 = 0.f, o0 = 0.f, o1 = 0.f;
#pragma unroll
    for (int k = 0; k < KNN; k++) {
        float e0 = __expf(p0[k] - m0);
        float e1 = __expf(p1[k] - m1);
        z0 += e0; z1 += e1;
        o0 = fmaf(e0, a0[k], o0);
        o1 = fmaf(e1, a1[k], o1);
    }
    out[(size_t)pt * 64 + c0] = o0 / z0;
    out[(size_t)pt * 64 + c1] = o1 / z1;
}

// ---------------------------------------------------------------------------
extern "C" void kernel_launch(void* const* d_in, const int* in_sizes, int n_in,
                              void* d_out, int out_size) {
    const float* xytp     = (const float*)d_in[0];
    const float* features = (const float*)d_in[1];
    const float* pe_w1    = (const float*)d_in[2];
    const float* pe_b1    = (const float*)d_in[3];
    const float* pe_w2    = (const float*)d_in[4];
    const float* pe_b2    = (const float*)d_in[5];
    const float* lt_w     = (const float*)d_in[6];
    const float* lt_b     = (const float*)d_in[7];
    const float* ln_g     = (const float*)d_in[8];
    const float* ln_b     = (const float*)d_in[9];
    float* out = (float*)d_out;

    zero_kernel<<<(4 * BINS) / 256, 256>>>();
    pack_kernel<<<BN / 256, 256>>>(xytp);
    scan_kernel<<<4, 1024>>>();
    scatter_kernel<<<BN / 256, 256>>>();
    repack_kernel<<<(BN / 2) / 256, 256>>>();
    dim3 sg(NPTS / 4, 4);
    seed_kernel<<<sg, 128>>>();
    dim3 wg(NPTS / 128, 4, 4);
    knn_win_kernel<<<wg, 128>>>();
    dim3 mg(NPTS / 128, 4);
    merge_kernel<<<mg, 128>>>();
    fb_kernel<<<mg, 128>>>();
    lt_kernel<<<BN / 32, 256>>>(features, lt_w, lt_b);
    fused_kernel<<<BN / 4, 128>>>(xytp, pe_w1, pe_b1, pe_w2, pe_b2, ln_g, ln_b, out);
}

// round 17
// speedup vs baseline: 1.5914x; 1.5914x over previous
#include <cuda_runtime.h>

#define BN    32768      // B*N
#define NPTS  8192
#define KNN   16
#define BINS  4096
#define XLO   (-6.0f)
#define BSCALE (BINS / 12.0f)
#define DELTA  (12.0f / BINS)
#define CAP    24        // per-lane survivor stack capacity

typedef unsigned long long ull;

__device__ float4 g_pts[BN];
__device__ int    g_hist[4 * BINS];
__device__ int    g_off [4 * BINS];
__device__ float4 g_sx  [BN];
__device__ int    g_sidx[BN];
__device__ ulonglong2 g_ta[BN / 2];
__device__ ulonglong2 g_tb[BN / 2];
__device__ float  g_T  [BN];                    // warm threshold, >= true d16
__device__ int2   g_rng[BN / 128];              // per query-group pair range
__device__ ull    g_pk[(size_t)BN * 4 * KNN];   // per-quarter sorted key lists
__device__ float  g_thr[BN];                    // merged d16 (fallback threshold)
__device__ int    g_flag[BN];
__device__ int    g_idx[BN * KNN];
__device__ float  g_lt[(size_t)BN * 192];

#define DINF 3.4e38f

// ---- packed f32x2 helpers (each lane independent exact fp32) --------------
__device__ __forceinline__ ull pk(float a, float b) {
    ull r; asm("mov.b64 %0, {%1,%2};" : "=l"(r) : "f"(a), "f"(b)); return r;
}
__device__ __forceinline__ void upk(ull v, float& a, float& b) {
    asm("mov.b64 {%0,%1}, %2;" : "=f"(a), "=f"(b) : "l"(v));
}
__device__ __forceinline__ ull fma2(ull a, ull b, ull c) {
    ull r; asm("fma.rn.f32x2 %0, %1, %2, %3;" : "=l"(r) : "l"(a), "l"(b), "l"(c)); return r;
}
__device__ __forceinline__ ull mul2(ull a, ull b) {
    ull r; asm("mul.rn.f32x2 %0, %1, %2;" : "=l"(r) : "l"(a), "l"(b)); return r;
}
__device__ __forceinline__ ull add2(ull a, ull b) {
    ull r; asm("add.rn.f32x2 %0, %1, %2;" : "=l"(r) : "l"(a), "l"(b)); return r;
}

// monotone order-preserving float -> u32 (+0.0f normalizes -0)
__device__ __forceinline__ unsigned fmap(float f) {
    unsigned b = __float_as_uint(f + 0.0f);
    return b ^ ((unsigned)((int)b >> 31) | 0x80000000u);
}
__device__ __forceinline__ float finv(unsigned u) {
    unsigned b = (u & 0x80000000u) ? (u ^ 0x80000000u) : ~u;
    return __uint_as_float(b);
}
__device__ __forceinline__ ull mkkey(float d, unsigned idx) {
    return (((ull)fmap(d)) << 32) | idx;
}

__device__ __forceinline__ int binof(float x) {
    int b = (int)((x - XLO) * BSCALE);
    return min(BINS - 1, max(0, b));
}

// sorted insert of u64 key into ascending 16-list (shift chain)
__device__ __forceinline__ void kins16(ull k, ull* B) {
    if (k >= B[15]) return;
    bool cs = true;
#pragma unroll
    for (int s = 15; s > 0; --s) {
        bool cp = k < B[s - 1];
        ull nb = cp ? B[s - 1] : (cs ? k : B[s]);
        B[s] = nb;
        cs = cp;
    }
    if (cs) B[0] = k;
}

// drain per-lane smem stack into register list; returns new float threshold
__device__ __forceinline__ float drainK(int& cnt, ull* stk, int tid, ull* B) {
    for (int i = 0;; i++) {
        if (!__ballot_sync(0xffffffffu, i < cnt)) break;
        if (i < cnt) {
            ull e = stk[i * 128 + tid];
            if (e < B[15]) kins16(e, B);
        }
    }
    cnt = 0;
    unsigned fk = (unsigned)(B[15] >> 32);
    return (fk == 0xFFFFFFFFu) ? DINF : finv(fk);
}

// ---------------------------------------------------------------------------
// 0. zero histogram
// ---------------------------------------------------------------------------
__global__ void zero_kernel() {
    int i = blockIdx.x * 256 + threadIdx.x;
    g_hist[i] = 0;
}

// ---------------------------------------------------------------------------
// 1. pack (x,y,z, sq) + histogram; sq = ((x*x)+(y*y))+(z*z) separately rounded
//    (exact XLA replication -- LOAD-BEARING)
// ---------------------------------------------------------------------------
__global__ void pack_kernel(const float* __restrict__ xytp) {
    int i = blockIdx.x * blockDim.x + threadIdx.x;
    float4 p = ((const float4*)xytp)[i];
    float xx = __fmul_rn(p.x, p.x);
    float yy = __fmul_rn(p.y, p.y);
    float zz = __fmul_rn(p.z, p.z);
    p.w = __fadd_rn(__fadd_rn(xx, yy), zz);
    g_pts[i] = p;
    atomicAdd(&g_hist[(i >> 13) * BINS + binof(p.x)], 1);
}

// ---------------------------------------------------------------------------
// 2. exclusive scan of per-batch histogram
// ---------------------------------------------------------------------------
__global__ void __launch_bounds__(1024) scan_kernel() {
    __shared__ int sv[1024];
    int b = blockIdx.x, t = threadIdx.x;
    int base = b * BINS + t * 4;
    int a0 = g_hist[base], a1 = g_hist[base + 1], a2 = g_hist[base + 2], a3 = g_hist[base + 3];
    int s = a0 + a1 + a2 + a3;
    sv[t] = s;
    __syncthreads();
    for (int off = 1; off < 1024; off <<= 1) {
        int v = (t >= off) ? sv[t - off] : 0;
        __syncthreads();
        sv[t] += v;
        __syncthreads();
    }
    int excl = sv[t] - s;
    g_off[base]     = excl;
    g_off[base + 1] = excl + a0;
    g_off[base + 2] = excl + a0 + a1;
    g_off[base + 3] = excl + a0 + a1 + a2;
}

// ---------------------------------------------------------------------------
// 3. scatter into x-bin order (afterwards g_off[bin] = end offset of bin)
// ---------------------------------------------------------------------------
__global__ void scatter_kernel() {
    int i = blockIdx.x * blockDim.x + threadIdx.x;
    int b = i >> 13;
    float4 p = g_pts[i];
    int pos = atomicAdd(&g_off[b * BINS + binof(p.x)], 1);
    g_sx  [b * NPTS + pos] = p;
    g_sidx[b * NPTS + pos] = i & (NPTS - 1);
}

// ---------------------------------------------------------------------------
// 4. pair-pack scattered points
// ---------------------------------------------------------------------------
__global__ void repack_kernel() {
    int j = blockIdx.x * blockDim.x + threadIdx.x;
    float4 p0 = g_sx[2 * j];
    float4 p1 = g_sx[2 * j + 1];
    ulonglong2 va, vb;
    va.x = pk(p0.x, p1.x);  va.y = pk(p0.y, p1.y);
    vb.x = pk(p0.z, p1.z);  vb.y = pk(p0.w, p1.w);
    g_ta[j] = va;  g_tb[j] = vb;
}

// ---------------------------------------------------------------------------
// 5. seed: WARP per query. 512-candidate x-window, exact distances, binary
//    search on fmap bits for T with count(d<=T) >= 16 in-window => T >= d16.
// ---------------------------------------------------------------------------
__global__ void __launch_bounds__(128) seed_kernel() {
    int b    = blockIdx.y;
    int wid  = threadIdx.x >> 5, lane = threadIdx.x & 31;
    int p    = blockIdx.x * 4 + wid;
    const ulonglong2* TA = g_ta + b * (NPTS / 2);
    const ulonglong2* TB = g_tb + b * (NPTS / 2);
    float4 me = g_sx[b * NPTS + p];
    ull m2x = pk(-2.0f * me.x, -2.0f * me.x);   // exact power-of-2 scale
    ull m2y = pk(-2.0f * me.y, -2.0f * me.y);
    ull m2z = pk(-2.0f * me.z, -2.0f * me.z);
    ull mw  = pk(me.w, me.w);

    int plo = min(max((p >> 1) - 128, 0), NPTS / 2 - 256);

    unsigned fm[16];
#pragma unroll
    for (int u = 0; u < 8; u++) {
        int j = plo + lane + 32 * u;            // coalesced across warp
        ulonglong2 A = TA[j], Z = TB[j];
        // exact reference arithmetic (validated bitwise):
        ull dn = fma2(m2z, Z.x, fma2(m2y, A.y, mul2(m2x, A.x)));
        ull dd = add2(add2(mw, Z.y), dn);
        float d0, d1; upk(dd, d0, d1);
        fm[2 * u]     = fmap(d0);
        fm[2 * u + 1] = fmap(d1);
    }

    unsigned lo = 0u, hi = 0xFFFFFFFFu;         // count(hi) = 512 >= 16
#pragma unroll
    for (int it = 0; it < 16; it++) {
        unsigned mid = lo + ((hi - lo) >> 1);
        int c = 0;
#pragma unroll
        for (int u = 0; u < 16; u++) c += (fm[u] <= mid);
        int tot = __reduce_add_sync(0xffffffffu, c);
        if (tot >= 16) hi = mid; else lo = mid + 1;
    }
    if (lane == 0) g_T[b * NPTS + p] = finv(hi);
}

// ---------------------------------------------------------------------------
// 5b. range: per 128-query group, the contiguous pair range [plo, phi) that
//     can contain any top-16 member. Per query: bins within x_q +-
//     sqrt(T_q + 1e-3) with one-bin slack (excluded points have gap >= r +
//     DELTA => gap^2 > T >= true d16 -- validated margin logic). Union over
//     group, bins -> offsets via post-scatter g_off (bin end offsets).
// ---------------------------------------------------------------------------
__global__ void __launch_bounds__(128) range_kernel() {
    __shared__ int sL[128], sR[128];
    int b = blockIdx.y;
    int q = blockIdx.x * 128 + threadIdx.x;
    float x = g_sx[b * NPTS + q].x;
    float T = g_T [b * NPTS + q];
    float r = sqrtf(T + 1e-3f);
    int Lb = (int)floorf((x - r - XLO) * BSCALE) - 1;
    int Rb = (int)floorf((x + r - XLO) * BSCALE) + 2;
    sL[threadIdx.x] = max(Lb, 0);
    sR[threadIdx.x] = min(Rb, BINS - 1);
    __syncthreads();
    for (int off = 64; off > 0; off >>= 1) {
        if (threadIdx.x < off) {
            sL[threadIdx.x] = min(sL[threadIdx.x], sL[threadIdx.x + off]);
            sR[threadIdx.x] = max(sR[threadIdx.x], sR[threadIdx.x + off]);
        }
        __syncthreads();
    }
    if (threadIdx.x == 0) {
        int BL = sL[0], BH = sR[0];
        int start = (BL <= 0) ? 0 : g_off[b * BINS + BL - 1];
        int end   = (BH >= BINS - 1) ? NPTS : g_off[b * BINS + BH];
        int2 rg;
        rg.x = start >> 1;                        // floor to pair
        rg.y = min(NPTS / 2, (end + 1) >> 1);     // ceil to pair
        g_rng[b * (NPTS / 128) + blockIdx.x] = rg;
    }
}

// ---------------------------------------------------------------------------
// 6. ranged kNN, warm threshold, fully pipelined (no in-loop gating).
//    Each quarter-block scans a tile-aligned disjoint slice of [plo, phi).
// ---------------------------------------------------------------------------
__global__ void __launch_bounds__(128) knn_win_kernel() {
    __shared__ ulonglong2 ta[128], tb[128];
    __shared__ int2       si2[128];
    __shared__ ull        stk[CAP * 128];

    int tid = threadIdx.x;
    int b   = blockIdx.z;
    int qtr = blockIdx.y;
    int qb  = blockIdx.x * 128;
    int q   = qb + tid;

    const ulonglong2* TA  = g_ta + b * (NPTS / 2);
    const ulonglong2* TB  = g_tb + b * (NPTS / 2);
    const int2*       SI2 = (const int2*)(g_sidx + b * NPTS);

    float4 me = g_sx[b * NPTS + q];
    float  T  = g_T [b * NPTS + q];
    ull m2x = pk(-2.0f * me.x, -2.0f * me.x);   // exact power-of-2 scale
    ull m2y = pk(-2.0f * me.y, -2.0f * me.y);
    ull m2z = pk(-2.0f * me.z, -2.0f * me.z);
    ull mw  = pk(me.w, me.w);

    int2 rg = g_rng[b * (NPTS / 128) + blockIdx.x];
    int qlen  = (((rg.y - rg.x + 3) >> 2) + 127) & ~127;   // tile-aligned split
    int start = rg.x + qtr * qlen;
    int end   = min(start + qlen, rg.y);

    ull B[KNN];
#pragma unroll
    for (int s = 0; s < KNN; s++) B[s] = ~0ULL;
    float b15f = T;      // warm threshold
    int cnt = 0;

    for (int t0 = start; t0 < end; t0 += 128) {
        int nv = min(128, end - t0);             // block-uniform
        __syncthreads();
        int pj = t0 + tid;
        if (pj >= NPTS / 2) pj = NPTS / 2 - 1;
        ta[tid]  = TA[pj];
        tb[tid]  = TB[pj];
        si2[tid] = SI2[pj];
        __syncthreads();
#pragma unroll 4
        for (int j = 0; j < nv; j += 2) {
            bool p1v = (j + 1 < nv);             // block-uniform
            ulonglong2 A0 = ta[j],     Z0 = tb[j];
            ulonglong2 A1 = ta[p1v ? j + 1 : j], Z1 = tb[p1v ? j + 1 : j];
            // exact reference arithmetic (validated bitwise):
            ull dn0 = fma2(m2z, Z0.x, fma2(m2y, A0.y, mul2(m2x, A0.x)));
            ull dn1 = fma2(m2z, Z1.x, fma2(m2y, A1.y, mul2(m2x, A1.x)));
            ull dd0 = add2(add2(mw, Z0.y), dn0);
            ull dd1 = add2(add2(mw, Z1.y), dn1);
            float d0, d1, d2, d3;
            upk(dd0, d0, d1);
            upk(dd1, d2, d3);
            int2 i0 = si2[j], i1 = si2[p1v ? j + 1 : j];
            if (d0 <= b15f) { stk[cnt * 128 + tid] = mkkey(d0, (unsigned)i0.x); cnt++; }
            if (d1 <= b15f) { stk[cnt * 128 + tid] = mkkey(d1, (unsigned)i0.y); cnt++; }
            if (p1v && d2 <= b15f) { stk[cnt * 128 + tid] = mkkey(d2, (unsigned)i1.x); cnt++; }
            if (p1v && d3 <= b15f) { stk[cnt * 128 + tid] = mkkey(d3, (unsigned)i1.y); cnt++; }
            if (__ballot_sync(0xffffffffu, cnt >= CAP - 4))
                b15f = fminf(T, drainK(cnt, stk, tid, B));
        }
        b15f = fminf(T, drainK(cnt, stk, tid, B));
    }

    size_t ob = ((size_t)(b * NPTS + q) * 4 + qtr) * KNN;
#pragma unroll
    for (int s = 0; s < KNN; s++) g_pk[ob + s] = B[s];
}

// ---------------------------------------------------------------------------
// 7. merge 4 quarter-lists -> top-16; per-query range-sufficiency check.
// ---------------------------------------------------------------------------
__global__ void __launch_bounds__(128) merge_kernel() {
    int b = blockIdx.y;
    int qb = blockIdx.x * 128;
    int q  = qb + threadIdx.x;
    const ull* pk4 = g_pk + ((size_t)(b * NPTS + q) * 4) * KNN;

    ull B[KNN];
#pragma unroll
    for (int s = 0; s < KNN; s++) B[s] = ~0ULL;
#pragma unroll
    for (int c = 0; c < 4; c++) {
        for (int s = 0; s < KNN; s++) {
            ull k = pk4[c * KNN + s];
            if (k >= B[15]) break;           // lists sorted ascending
            kins16(k, B);
        }
    }

    float mex = g_sx[b * NPTS + q].x;
    int2 rg = g_rng[b * (NPTS / 128) + blockIdx.x];
    float d16 = finv((unsigned)(B[15] >> 32));

    bool safe_l = (rg.x == 0);
    if (!safe_l) {
        int bl = binof(g_sx[b * NPTS + 2 * rg.x].x);
        float gap = mex - (XLO + (bl + 1) * DELTA);
        safe_l = (bl < BINS - 1) && (gap > 0.0f) && (gap * gap > d16 + 1e-3f);
    }
    bool safe_r = (rg.y == NPTS / 2);
    if (!safe_r) {
        int br = binof(g_sx[b * NPTS + 2 * rg.y - 1].x);
        float gap = (XLO + br * DELTA) - mex;
        safe_r = (br > 0) && (gap > 0.0f) && (gap * gap > d16 + 1e-3f);
    }

    int orig = g_sidx[b * NPTS + q];
    int ob = (b * NPTS + orig) * KNN;
#pragma unroll
    for (int s = 0; s < KNN; s++)
        g_idx[ob + s] = (int)(unsigned)(B[s] & 0xffffffffu);
    g_flag[b * NPTS + q] = (safe_l && safe_r) ? 0 : 1;
    g_thr [b * NPTS + q] = d16;              // valid upper bound on true d16
}

// ---------------------------------------------------------------------------
// 8. fallback: warp-cooperative exact rescan for flagged queries.
// ---------------------------------------------------------------------------
__global__ void __launch_bounds__(128) fb_kernel() {
    __shared__ ull ssv[4][96];
    __shared__ int scnt[4];
    int tid = threadIdx.x, w = tid >> 5, lane = tid & 31;
    int b = blockIdx.y;
    int qbase = blockIdx.x * 128 + w * 32;
    int fl = g_flag[b * NPTS + qbase + lane];
    unsigned mask = __ballot_sync(0xffffffffu, fl != 0);
    if (!mask) return;

    const ulonglong2* TA  = g_ta + b * (NPTS / 2);
    const ulonglong2* TB  = g_tb + b * (NPTS / 2);
    const int2*       SI2 = (const int2*)(g_sidx + b * NPTS);

    while (mask) {
        int li = __ffs(mask) - 1; mask &= mask - 1;
        int fq = qbase + li;
        float4 me = g_sx[b * NPTS + fq];
        float  T  = g_thr[b * NPTS + fq];
        ull m2x = pk(-2.0f * me.x, -2.0f * me.x);
        ull m2y = pk(-2.0f * me.y, -2.0f * me.y);
        ull m2z = pk(-2.0f * me.z, -2.0f * me.z);
        ull mw  = pk(me.w, me.w);
        if (lane == 0) scnt[w] = 0;
        __syncwarp();
        for (int pj = lane; pj < NPTS / 2; pj += 32) {
            ulonglong2 A = TA[pj], Z = TB[pj];
            ull dn = fma2(m2z, Z.x, fma2(m2y, A.y, mul2(m2x, A.x)));
            ull dd = add2(add2(mw, Z.y), dn);
            float d0, d1; upk(dd, d0, d1);
            int2 ii = SI2[pj];
            if (d0 <= T) { int p = atomicAdd(&scnt[w], 1); if (p < 96) ssv[w][p] = mkkey(d0, (unsigned)ii.x); }
            if (d1 <= T) { int p = atomicAdd(&scnt[w], 1); if (p < 96) ssv[w][p] = mkkey(d1, (unsigned)ii.y); }
        }
        __syncwarp();
        if (lane == 0) {
            ull B[KNN];
#pragma unroll
            for (int s = 0; s < KNN; s++) B[s] = ~0ULL;
            int n = scnt[w];
            if (n <= 96) {
                for (int i = 0; i < n; i++) kins16(ssv[w][i], B);
            } else {                         // vanishing-probability overflow
                for (int pj = 0; pj < NPTS / 2; pj++) {
                    ulonglong2 A = TA[pj], Z = TB[pj];
                    ull dn = fma2(m2z, Z.x, fma2(m2y, A.y, mul2(m2x, A.x)));
                    ull dd = add2(add2(mw, Z.y), dn);
                    float d0, d1; upk(dd, d0, d1);
                    int2 ii = SI2[pj];
                    ull k0 = mkkey(d0, (unsigned)ii.x);
                    ull k1 = mkkey(d1, (unsigned)ii.y);
                    if (k0 < B[15]) kins16(k0, B);
                    if (k1 < B[15]) kins16(k1, B);
                }
            }
            int orig = g_sidx[b * NPTS + fq];
            int ob = (b * NPTS + orig) * KNN;
            for (int s = 0; s < KNN; s++)
                g_idx[ob + s] = (int)(unsigned)(B[s] & 0xffffffffu);
        }
        __syncwarp();
    }
}

// ---------------------------------------------------------------------------
// 9. lt = features @ lt_w + lt_b, f32x2, 4 independent partial accumulators
// ---------------------------------------------------------------------------
__global__ void __launch_bounds__(256) lt_kernel(const float* __restrict__ feat,
                                                 const float* __restrict__ w,
                                                 const float* __restrict__ bias) {
    __shared__ __align__(16) float fs[32][64];
    int row0 = blockIdx.x * 32;
    for (int i = threadIdx.x; i < 32 * 64; i += 256)
        fs[i >> 6][i & 63] = feat[row0 * 64 + i];
    __syncthreads();

    int c = threadIdx.x;
    if (c < 192) {
        ull w2[32];
#pragma unroll
        for (int k = 0; k < 32; k++)
            w2[k] = pk(w[(2 * k) * 192 + c], w[(2 * k + 1) * 192 + c]);
        float bc = bias[c];
        for (int r = 0; r < 32; r++) {
            ull a0 = pk(bc, 0.0f), a1 = pk(0.f, 0.f), a2 = a1, a3 = a1;
            const ull* fr = (const ull*)&fs[r][0];
#pragma unroll
            for (int k = 0; k < 32; k += 4) {
                a0 = fma2(fr[k],     w2[k],     a0);
                a1 = fma2(fr[k + 1], w2[k + 1], a1);
                a2 = fma2(fr[k + 2], w2[k + 2], a2);
                a3 = fma2(fr[k + 3], w2[k + 3], a3);
            }
            ull acc = add2(add2(a0, a1), add2(a2, a3));
            float ax, ay; upk(acc, ax, ay);
            g_lt[(size_t)(row0 + r) * 192 + c] = ax + ay;
        }
    }
}

// ---------------------------------------------------------------------------
// 10. fused: gather -> delta MLP -> LN -> softmax(k) -> output
// ---------------------------------------------------------------------------
__global__ void __launch_bounds__(128) fused_kernel(
    const float* __restrict__ xytp,
    const float* __restrict__ pe_w1, const float* __restrict__ pe_b1,
    const float* __restrict__ pe_w2, const float* __restrict__ pe_b2,
    const float* __restrict__ ln_g,  const float* __restrict__ ln_b,
    float* __restrict__ out)
{
    __shared__ float  W2s[64 * 64];
    __shared__ float4 rels[4][16];
    __shared__ __align__(16) float HS[4][64][20];

    int tid = threadIdx.x, w = tid >> 5, lane = tid & 31;
    for (int i = tid; i < 4096; i += 128) W2s[i] = pe_w2[i];

    int pt = blockIdx.x * 4 + w;
    int b  = pt >> 13;
    int c0 = lane, c1 = lane + 32;

    float w1a[4], w1b[4];
#pragma unroll
    for (int d = 0; d < 4; d++) { w1a[d] = pe_w1[d * 64 + c0]; w1b[d] = pe_w1[d * 64 + c1]; }
    float b10 = pe_b1[c0], b11 = pe_b1[c1];
    float b20 = pe_b2[c0], b21 = pe_b2[c1];
    float g0  = ln_g[c0],  g1  = ln_g[c1];
    float q0  = ln_b[c0],  q1  = ln_b[c1];

    const int* idxp = g_idx + pt * KNN;
    float4 ctr = ((const float4*)xytp)[pt];
    if (lane < 16) {
        int nb = idxp[lane];
        float4 p = ((const float4*)xytp)[b * NPTS + nb];
        rels[w][lane] = make_float4(ctr.x - p.x, ctr.y - p.y, ctr.z - p.z, ctr.w - p.w);
    }
    __syncthreads();

#pragma unroll
    for (int k = 0; k < KNN; k++) {
        float4 r = rels[w][k];
        float h0 = fmaf(r.w, w1a[3], fmaf(r.z, w1a[2], fmaf(r.y, w1a[1], fmaf(r.x, w1a[0], b10))));
        float h1 = fmaf(r.w, w1b[3], fmaf(r.z, w1b[2], fmaf(r.y, w1b[1], fmaf(r.x, w1b[0], b11))));
        HS[w][c0][k] = fmaxf(h0, 0.f);
        HS[w][c1][k] = fmaxf(h1, 0.f);
    }
    __syncwarp();

    ull d0p[8], d1p[8];
#pragma unroll
    for (int m = 0; m < 8; m++) { d0p[m] = pk(b20, b20); d1p[m] = pk(b21, b21); }
#pragma unroll 4
    for (int j = 0; j < 64; j++) {
        ull wv0 = pk(W2s[j * 64 + c0], W2s[j * 64 + c0]);
        ull wv1 = pk(W2s[j * 64 + c1], W2s[j * 64 + c1]);
        const ulonglong2* hr = (const ulonglong2*)&HS[w][j][0];
        ulonglong2 ha = hr[0], hb = hr[1];
        ull hp[4] = { ha.x, ha.y, hb.x, hb.y };
#pragma unroll
        for (int m = 0; m < 4; m++) {
            d0p[m] = fma2(hp[m], wv0, d0p[m]);
            d1p[m] = fma2(hp[m], wv1, d1p[m]);
        }
        ulonglong2 hc = hr[2], hd = hr[3];
        ull hq[4] = { hc.x, hc.y, hd.x, hd.y };
#pragma unroll
        for (int m = 0; m < 4; m++) {
            d0p[m + 4] = fma2(hq[m], wv0, d0p[m + 4]);
            d1p[m + 4] = fma2(hq[m], wv1, d1p[m + 4]);
        }
    }
    float d0[KNN], d1[KNN];
#pragma unroll
    for (int m = 0; m < 8; m++) {
        upk(d0p[m], d0[2 * m], d0[2 * m + 1]);
        upk(d1p[m], d1[2 * m], d1[2 * m + 1]);
    }

    const float* ltb = g_lt + (size_t)(b * NPTS) * 192;
    int n = pt & (NPTS - 1);
    float vp0 = ltb[(size_t)n * 192 + c0];
    float vp1 = ltb[(size_t)n * 192 + c1];

    float a0[KNN], a1[KNN], p0[KNN], p1[KNN];
#pragma unroll
    for (int k = 0; k < KNN; k++) {
        int nb = idxp[k];
        const float* lr = ltb + (size_t)nb * 192;
        float ps0 = lr[64 + c0],  ps1 = lr[64 + c1];
        float al0 = lr[128 + c0], al1 = lr[128 + c1];
        float pr0 = (vp0 - ps0) + d0[k];
        float pr1 = (vp1 - ps1) + d1[k];
        a0[k] = al0 + d0[k];
        a1[k] = al1 + d1[k];
        float sm = pr0 + pr1;
        float sq = fmaf(pr0, pr0, pr1 * pr1);
#pragma unroll
        for (int off = 16; off > 0; off >>= 1) {
            sm += __shfl_xor_sync(0xffffffffu, sm, off);
            sq += __shfl_xor_sync(0xffffffffu, sq, off);
        }
        float mu  = sm * (1.0f / 64.0f);
        float var = fmaf(-mu, mu, sq * (1.0f / 64.0f));
        float rs  = rsqrtf(var + 1e-5f);
        p0[k] = fmaf((pr0 - mu) * rs, g0, q0) * 0.125f;
        p1[k] = fmaf((pr1 - mu) * rs, g1, q1) * 0.125f;
    }

    float m0 = -3.4e38f, m1 = -3.4e38f;
#pragma unroll
    for (int k = 0; k < KNN; k++) { m0 = fmaxf(m0, p0[k]); m1 = fmaxf(m1, p1[k]); }
    float z0 = 0.f, z1 = 0.f, o0 = 0.f, o1 = 0.f;
#pragma unroll
    for (int k = 0; k < KNN; k++) {
        float e0 = __expf(p0[k] - m0);
        float e1 = __expf(p1[k] - m1);
        z0 += e0; z1 += e1;
        o0 = fmaf(e0, a0[k], o0);
        o1 = fmaf(e1, a1[k], o1);
    }
    out[(size_t)pt * 64 + c0] = o0 / z0;
    out[(size_t)pt * 64 + c1] = o1 / z1;
}

// ---------------------------------------------------------------------------
extern "C" void kernel_launch(void* const* d_in, const int* in_sizes, int n_in,
                              void* d_out, int out_size) {
    const float* xytp     = (const float*)d_in[0];
    const float* features = (const float*)d_in[1];
    const float* pe_w1    = (const float*)d_in[2];
    const float* pe_b1    = (const float*)d_in[3];
    const float* pe_w2    = (const float*)d_in[4];
    const float* pe_b2    = (const float*)d_in[5];
    const float* lt_w     = (const float*)d_in[6];
    const float* lt_b     = (const float*)d_in[7];
    const float* ln_g     = (const float*)d_in[8];
    const float* ln_b     = (const float*)d_in[9];
    float* out = (float*)d_out;

    zero_kernel<<<(4 * BINS) / 256, 256>>>();
    pack_kernel<<<BN / 256, 256>>>(xytp);
    scan_kernel<<<4, 1024>>>();
    scatter_kernel<<<BN / 256, 256>>>();
    repack_kernel<<<(BN / 2) / 256, 256>>>();
    dim3 sg(NPTS / 4, 4);
    seed_kernel<<<sg, 128>>>();
    dim3 rg(NPTS / 128, 4);
    range_kernel<<<rg, 128>>>();
    dim3 wg(NPTS / 128, 4, 4);
    knn_win_kernel<<<wg, 128>>>();
    dim3 mg(NPTS / 128, 4);
    merge_kernel<<<mg, 128>>>();
    fb_kernel<<<mg, 128>>>();
    lt_kernel<<<BN / 32, 256>>>(features, lt_w, lt_b);
    fused_kernel<<<BN / 4, 128>>>(xytp, pe_w1, pe_b1, pe_w2, pe_b2, ln_g, ln_b, out);
}